// round 11
// baseline (speedup 1.0000x reference)
#include <cuda_runtime.h>
#include <cstdint>

// dense_image_warp: out[b,y,x,c] = bilinear(image[b], y - flow[b,y,x,0], x - flow[b,y,x,1])
// B=8, H=512, W=512, C=16, fp32.
//
// Quarter-warp gather: 4 lanes cooperate on one pixel. TL+TR of a sample are
// 128 contiguous bytes (adjacent pixels in [b,y,x,c]); each lane LDG.256s one
// 32B quarter of that row (and of the bottom row), so gather instructions are
// made of contiguous 128B chunks -> fewer L1 wavefronts per useful byte.
// Channels are redistributed through smem, then each lane interpolates and
// stores one channel group (coalesced 64B per pixel-quad).
//
// Block = 256 threads; 16x16 pixel tile; 4 passes x 64 pixels.

#define Hh 512
#define Ww 512
#define PXW 36   // floats per pixel row buffer (32 + 4 pad) to stagger banks

#define LDG256(r, p)                                                        \
    asm volatile("ld.global.nc.v8.f32 {%0,%1,%2,%3,%4,%5,%6,%7}, [%8];"      \
        : "=f"(r[0]), "=f"(r[1]), "=f"(r[2]), "=f"(r[3]),                    \
          "=f"(r[4]), "=f"(r[5]), "=f"(r[6]), "=f"(r[7])                     \
        : "l"(p))

__global__ __launch_bounds__(256) void warp_kernel_quad(
    const float* __restrict__ img,     // [B,H,W,C]
    const float2* __restrict__ flow2,  // [B,H,W,2]
    float4* __restrict__ out4)
{
    __shared__ float2 sflow[256];          // 16x16 flow tile
    __shared__ float  sT[64 * PXW];        // top rows (TL|TR), 64 px per pass
    __shared__ float  sB[64 * PXW];        // bottom rows (BL|BR)

    int t  = threadIdx.x;
    int q  = t & 3;                        // lane-in-quad == channel group
    int px = t >> 2;                       // pixel slot within pass: 0..63

    int x0 = blockIdx.x * 16;
    int y0 = blockIdx.y * 16;
    int b  = blockIdx.z;

    // ---- stage 16x16 flow tile ----
    {
        int fxp = x0 + (t & 15);
        int fyp = y0 + (t >> 4);
        int fp  = (((b << 9) + fyp) << 9) + fxp;
        sflow[t] = __ldcs(&flow2[fp]);
    }
    __syncthreads();

    int lxp = px & 15;                     // pixel x within tile
    int x   = x0 + lxp;

    #pragma unroll
    for (int p = 0; p < 4; p++) {
        int ty = (p << 2) + (px >> 4);     // tile row 0..15
        int y  = y0 + ty;

        float2 f = sflow[(ty << 4) + lxp];
        float qy = (float)y - f.x;
        float qx = (float)x - f.y;

        float fy = fminf(fmaxf(floorf(qy), 0.0f), (float)(Hh - 2));
        float fx = fminf(fmaxf(floorf(qx), 0.0f), (float)(Ww - 2));
        float ay = fminf(fmaxf(qy - fy, 0.0f), 1.0f);
        float ax = fminf(fmaxf(qx - fx, 0.0f), 1.0f);
        int iy = (int)fy;
        int ix = (int)fx;

        // ---- gather phase: quad reads top 128B (TL|TR) and bottom 128B ----
        const char* tb = (const char*)img
            + ((size_t)((((b << 9) + iy) << 9) + ix) << 6) + (q << 5);
        float t8[8], b8[8];
        LDG256(t8, tb);
        LDG256(b8, tb + (Ww << 6));

        // scatter into smem: floats [0..15]=TL c0-15, [16..31]=TR c0-15
        {
            float4* dT = (float4*)&sT[px * PXW + (q << 3)];
            float4* dB = (float4*)&sB[px * PXW + (q << 3)];
            dT[0] = make_float4(t8[0], t8[1], t8[2], t8[3]);
            dT[1] = make_float4(t8[4], t8[5], t8[6], t8[7]);
            dB[0] = make_float4(b8[0], b8[1], b8[2], b8[3]);
            dB[1] = make_float4(b8[4], b8[5], b8[6], b8[7]);
        }
        __syncthreads();

        // ---- compute phase: lane q handles channel group q of its pixel ----
        {
            const float4* pT = (const float4*)&sT[px * PXW];
            const float4* pB = (const float4*)&sB[px * PXW];
            float4 tl = pT[q];
            float4 tr = pT[q + 4];
            float4 bl = pB[q];
            float4 br = pB[q + 4];

            float4 top, bot, r;
            top.x = fmaf(ax, tr.x - tl.x, tl.x);
            top.y = fmaf(ax, tr.y - tl.y, tl.y);
            top.z = fmaf(ax, tr.z - tl.z, tl.z);
            top.w = fmaf(ax, tr.w - tl.w, tl.w);
            bot.x = fmaf(ax, br.x - bl.x, bl.x);
            bot.y = fmaf(ax, br.y - bl.y, bl.y);
            bot.z = fmaf(ax, br.z - bl.z, bl.z);
            bot.w = fmaf(ax, br.w - bl.w, bl.w);
            r.x = fmaf(ay, bot.x - top.x, top.x);
            r.y = fmaf(ay, bot.y - top.y, top.y);
            r.z = fmaf(ay, bot.z - top.z, top.z);
            r.w = fmaf(ay, bot.w - top.w, top.w);

            int op = (((b << 9) + y) << 9) + x;
            __stcs(&out4[(op << 2) + q], r);
        }
        __syncthreads();   // protect sT/sB reuse next pass
    }
}

extern "C" void kernel_launch(void* const* d_in, const int* in_sizes, int n_in,
                              void* d_out, int out_size)
{
    const float*  img   = (const float*)d_in[0];
    const float2* flow2 = (const float2*)d_in[1];
    float4* out4 = (float4*)d_out;

    dim3 grid(Ww / 16, Hh / 16, 8);
    warp_kernel_quad<<<grid, 256>>>(img, flow2, out4);
}

// round 12
// speedup vs baseline: 1.4439x; 1.4439x over previous
#include <cuda_runtime.h>
#include <cstdint>

// dense_image_warp: out[b,y,x,c] = bilinear(image[b], y - flow[b,y,x,0], x - flow[b,y,x,1])
// B=8, H=512, W=512, C=16, fp32.
// R9 base (16x16 tile, smem flow, smem out tile + cp.async.bulk stores) with a
// 2-stage software pipeline: iteration i+1's four gathers are issued before
// iteration i's interpolation, doubling outstanding gather bytes per warp
// while keeping addresses/locality identical.

#define Hh 512
#define Ww 512

__global__ __launch_bounds__(256, 5) void warp_kernel_pipe(
    const float4* __restrict__ img4,   // image as float4 (4 channels per group)
    const float2* __restrict__ flow2,  // flow as float2 per pixel
    float4* __restrict__ out4)
{
    __shared__ float2 sflow[256];                  // 16x16 flow tile
    __shared__ alignas(128) float4 sout[16 * 64];  // 16 KB output tile

    int t  = threadIdx.x;
    int cg = t & 3;
    int lx = (t >> 2) & 15;
    int ly = t >> 6;                   // 0..3

    int x0 = blockIdx.x * 16;
    int y0 = blockIdx.y * 16;
    int b  = blockIdx.z;
    int x  = x0 + lx;

    // ---- stage flow tile ----
    {
        int fxp = x0 + (t & 15);
        int fyp = y0 + (t >> 4);
        int fp  = (((b << 9) + fyp) << 9) + fxp;
        sflow[t] = __ldcs(&flow2[fp]);
    }
    __syncthreads();

    float4 tl[2], tr[2], bl[2], br[2];
    float  axv[2], ayv[2];

    // helper expanded manually: compute sample for iteration 'it' into slot s
    #define ISSUE(it_, s_)                                                    \
    {                                                                         \
        int ty_ = (it_) * 4 + ly;                                             \
        int y_  = y0 + ty_;                                                   \
        float2 f_ = sflow[(ty_ << 4) + lx];                                   \
        float qy_ = (float)y_ - f_.x;                                         \
        float qx_ = (float)x  - f_.y;                                         \
        float fy_ = fminf(fmaxf(floorf(qy_), 0.0f), (float)(Hh - 2));         \
        float fx_ = fminf(fmaxf(floorf(qx_), 0.0f), (float)(Ww - 2));         \
        ayv[s_] = fminf(fmaxf(qy_ - fy_, 0.0f), 1.0f);                        \
        axv[s_] = fminf(fmaxf(qx_ - fx_, 0.0f), 1.0f);                        \
        int iy_ = (int)fy_;                                                   \
        int ix_ = (int)fx_;                                                   \
        int base_ = (((b << 9) + iy_) << 9) + ix_;                            \
        int a_tl_ = (base_ << 2) + cg;                                        \
        int a_bl_ = a_tl_ + (Ww << 2);                                        \
        tl[s_] = __ldg(&img4[a_tl_]);                                         \
        tr[s_] = __ldg(&img4[a_tl_ + 4]);                                     \
        bl[s_] = __ldg(&img4[a_bl_]);                                         \
        br[s_] = __ldg(&img4[a_bl_ + 4]);                                     \
    }

    #define CONSUME(it_, s_)                                                  \
    {                                                                         \
        float ax_ = axv[s_], ay_ = ayv[s_];                                   \
        float4 TL = tl[s_], TR = tr[s_], BL = bl[s_], BR = br[s_];            \
        float4 top, bot, r;                                                   \
        top.x = fmaf(ax_, TR.x - TL.x, TL.x);                                 \
        top.y = fmaf(ax_, TR.y - TL.y, TL.y);                                 \
        top.z = fmaf(ax_, TR.z - TL.z, TL.z);                                 \
        top.w = fmaf(ax_, TR.w - TL.w, TL.w);                                 \
        bot.x = fmaf(ax_, BR.x - BL.x, BL.x);                                 \
        bot.y = fmaf(ax_, BR.y - BL.y, BL.y);                                 \
        bot.z = fmaf(ax_, BR.z - BL.z, BL.z);                                 \
        bot.w = fmaf(ax_, BR.w - BL.w, BL.w);                                 \
        r.x = fmaf(ay_, bot.x - top.x, top.x);                                \
        r.y = fmaf(ay_, bot.y - top.y, top.y);                                \
        r.z = fmaf(ay_, bot.z - top.z, top.z);                                \
        r.w = fmaf(ay_, bot.w - top.w, top.w);                                \
        int ty_ = (it_) * 4 + ly;                                             \
        sout[(ty_ << 6) + (lx << 2) + cg] = r;                                \
    }

    ISSUE(0, 0)
    ISSUE(1, 1)
    CONSUME(0, 0)
    ISSUE(2, 0)
    CONSUME(1, 1)
    ISSUE(3, 1)
    CONSUME(2, 0)
    CONSUME(3, 1)

    __syncthreads();
    asm volatile("fence.proxy.async.shared::cta;" ::: "memory");

    // threads 0..15 each push one 1KB row to global via bulk async copy
    if (t < 16) {
        int y = y0 + t;
        char* g = (char*)out4 + ((size_t)((((b << 9) + y) << 9) + x0)) * 64;
        uint32_t s = (uint32_t)__cvta_generic_to_shared(&sout[t << 6]);
        asm volatile("cp.async.bulk.global.shared::cta.bulk_group [%0], [%1], %2;\n"
                     :: "l"(g), "r"(s), "r"(1024) : "memory");
        asm volatile("cp.async.bulk.commit_group;\n" ::: "memory");
        asm volatile("cp.async.bulk.wait_group 0;\n" ::: "memory");
    }
}

extern "C" void kernel_launch(void* const* d_in, const int* in_sizes, int n_in,
                              void* d_out, int out_size)
{
    const float4* img4  = (const float4*)d_in[0];
    const float2* flow2 = (const float2*)d_in[1];
    float4* out4 = (float4*)d_out;

    dim3 grid(Ww / 16, Hh / 16, 8);
    warp_kernel_pipe<<<grid, 256>>>(img4, flow2, out4);
}

// round 14
// speedup vs baseline: 1.5084x; 1.0446x over previous
#include <cuda_runtime.h>
#include <cstdint>

// dense_image_warp: out[b,y,x,c] = bilinear(image[b], y - flow[b,y,x,0], x - flow[b,y,x,1])
// B=8, H=512, W=512, C=16, fp32.
// R9 structure (16x16 tile, smem flow, smem out tile + cp.async.bulk stores)
// + L2 evict-last policy (createpolicy + cache_hint) on image gathers: the
// image (134MB) nearly fits in L2 (126MB) and L2 persists across graph
// replays, so prioritizing image lines over the write-once output/flow
// streams converts DRAM read misses into L2 hits in steady state.

#define Hh 512
#define Ww 512

__device__ __forceinline__ float4 ldg_el(const float4* p, uint64_t pol) {
    float4 v;
    asm volatile("ld.global.nc.L2::cache_hint.v4.f32 {%0,%1,%2,%3}, [%4], %5;"
                 : "=f"(v.x), "=f"(v.y), "=f"(v.z), "=f"(v.w)
                 : "l"(p), "l"(pol));
    return v;
}

__global__ __launch_bounds__(256) void warp_kernel_el(
    const float4* __restrict__ img4,   // image as float4 (4 channels per group)
    const float2* __restrict__ flow2,  // flow as float2 per pixel
    float4* __restrict__ out4)
{
    __shared__ float2 sflow[256];                  // 16x16 flow tile
    __shared__ alignas(128) float4 sout[16 * 64];  // 16 KB output tile

    uint64_t pol;
    asm volatile("createpolicy.fractional.L2::evict_last.b64 %0, 1.0;" : "=l"(pol));

    int t  = threadIdx.x;
    int cg = t & 3;
    int lx = (t >> 2) & 15;
    int ly = t >> 6;                   // 0..3

    int x0 = blockIdx.x * 16;
    int y0 = blockIdx.y * 16;
    int b  = blockIdx.z;
    int x  = x0 + lx;

    // ---- stage flow tile (read-once -> evict-first) ----
    {
        int fxp = x0 + (t & 15);
        int fyp = y0 + (t >> 4);
        int fp  = (((b << 9) + fyp) << 9) + fxp;
        sflow[t] = __ldcs(&flow2[fp]);
    }
    __syncthreads();

    #pragma unroll
    for (int it = 0; it < 4; it++) {
        int ty = it * 4 + ly;          // row within tile: 0..15
        int y  = y0 + ty;

        float2 f = sflow[(ty << 4) + lx];
        float qy = (float)y - f.x;
        float qx = (float)x - f.y;

        float fy = fminf(fmaxf(floorf(qy), 0.0f), (float)(Hh - 2));
        float fx = fminf(fmaxf(floorf(qx), 0.0f), (float)(Ww - 2));
        float ay = fminf(fmaxf(qy - fy, 0.0f), 1.0f);
        float ax = fminf(fmaxf(qx - fx, 0.0f), 1.0f);
        int iy = (int)fy;
        int ix = (int)fx;

        int base = (((b << 9) + iy) << 9) + ix;   // TL pixel index
        int a_tl = (base << 2) + cg;
        int a_bl = a_tl + (Ww << 2);

        float4 tl = ldg_el(&img4[a_tl], pol);
        float4 tr = ldg_el(&img4[a_tl + 4], pol);
        float4 bl = ldg_el(&img4[a_bl], pol);
        float4 br = ldg_el(&img4[a_bl + 4], pol);

        float4 top, bot, r;
        top.x = fmaf(ax, tr.x - tl.x, tl.x);
        top.y = fmaf(ax, tr.y - tl.y, tl.y);
        top.z = fmaf(ax, tr.z - tl.z, tl.z);
        top.w = fmaf(ax, tr.w - tl.w, tl.w);
        bot.x = fmaf(ax, br.x - bl.x, bl.x);
        bot.y = fmaf(ax, br.y - bl.y, bl.y);
        bot.z = fmaf(ax, br.z - bl.z, bl.z);
        bot.w = fmaf(ax, br.w - bl.w, bl.w);
        r.x = fmaf(ay, bot.x - top.x, top.x);
        r.y = fmaf(ay, bot.y - top.y, top.y);
        r.z = fmaf(ay, bot.z - top.z, top.z);
        r.w = fmaf(ay, bot.w - top.w, top.w);

        sout[(ty << 6) + (lx << 2) + cg] = r;
    }

    __syncthreads();
    asm volatile("fence.proxy.async.shared::cta;" ::: "memory");

    // threads 0..15 each push one 1KB row to global via bulk async copy
    if (t < 16) {
        int y = y0 + t;
        char* g = (char*)out4 + ((size_t)((((b << 9) + y) << 9) + x0)) * 64;
        uint32_t s = (uint32_t)__cvta_generic_to_shared(&sout[t << 6]);
        asm volatile("cp.async.bulk.global.shared::cta.bulk_group [%0], [%1], %2;\n"
                     :: "l"(g), "r"(s), "r"(1024) : "memory");
        asm volatile("cp.async.bulk.commit_group;\n" ::: "memory");
        asm volatile("cp.async.bulk.wait_group 0;\n" ::: "memory");
    }
}

extern "C" void kernel_launch(void* const* d_in, const int* in_sizes, int n_in,
                              void* d_out, int out_size)
{
    const float4* img4  = (const float4*)d_in[0];
    const float2* flow2 = (const float2*)d_in[1];
    float4* out4 = (float4*)d_out;

    dim3 grid(Ww / 16, Hh / 16, 8);
    warp_kernel_el<<<grid, 256>>>(img4, flow2, out4);
}